// round 1
// baseline (speedup 1.0000x reference)
#include <cuda_runtime.h>

#define BB 128
#define NN 512
#define FF 128

// Scratch (allocation-free rule: __device__ globals)
__device__ float g_xw[BB * NN * FF];     // dnorm-prescaled X@W
__device__ float g_dnorm[BB * NN];

// ---------------- f32x2 helpers (Blackwell packed fp32) ----------------
__device__ __forceinline__ unsigned long long pack2(float a) {
    unsigned long long r;
    asm("mov.b64 %0, {%1, %1};" : "=l"(r) : "f"(a));
    return r;
}
__device__ __forceinline__ unsigned long long ffma2(unsigned long long a,
                                                    unsigned long long b,
                                                    unsigned long long c) {
    unsigned long long d;
    asm("fma.rn.f32x2 %0, %1, %2, %3;" : "=l"(d) : "l"(a), "l"(b), "l"(c));
    return d;
}

// ---------------- Kernel 1: degree + rsqrt norm ----------------
// one warp per adjacency row (B*N rows, each 512 floats)
__global__ void deg_kernel(const float* __restrict__ adj) {
    int row  = blockIdx.x * 8 + (threadIdx.x >> 5);
    int lane = threadIdx.x & 31;
    const float4* p = (const float4*)(adj + (size_t)row * NN);
    float s = 0.f;
#pragma unroll
    for (int i = 0; i < 4; i++) {
        float4 v = p[lane + i * 32];
        s += (v.x + v.y) + (v.z + v.w);
    }
#pragma unroll
    for (int o = 16; o; o >>= 1) s += __shfl_xor_sync(0xffffffffu, s, o);
    if (lane == 0) g_dnorm[row] = (s > 0.f) ? rsqrtf(s) : 0.f;
}

// ---------------- shared tiling constants ----------------
#define PAD 4                     // sA row stride 132 floats (16B aligned)
#define SA_STRIDE (FF + PAD)
#define SMEM_FLOATS (128 * SA_STRIDE + 128 * FF)
#define SMEM_BYTES (SMEM_FLOATS * 4)

// ---------------- Kernel 2: xw = dnorm ⊙ (x @ W) ----------------
// block: 128 flattened rows x 128 cols, k = 128 (single tile)
__global__ __launch_bounds__(256, 1)
void xw_kernel(const float* __restrict__ x, const float* __restrict__ W) {
    extern __shared__ float smem[];
    float* sA = smem;                       // [128][SA_STRIDE], row-major [row][k]
    float* sB = smem + 128 * SA_STRIDE;     // [128][128], [k][g]

    int tid = threadIdx.x;
    int r0  = blockIdx.x * 128;

    // load x tile (coalesced float4), direct layout
    const float4* gx = (const float4*)(x + (size_t)r0 * FF);
    const float4* gw = (const float4*)W;
#pragma unroll
    for (int i = 0; i < 16; i++) {
        int f   = tid + i * 256;            // float4 idx within 128x128 tile
        int row = f >> 5, kq = f & 31;
        float4 v = gx[f];
        *(float4*)&sA[row * SA_STRIDE + kq * 4] = v;
        float4 w = gw[f];                   // W is [k][g] row-major already
        *(float4*)&sB[f * 4] = w;
    }
    __syncthreads();

    int tx = tid & 15, ty = tid >> 4;
    int rb = ty * 8, gb = tx * 8;
    unsigned long long c[8][4];
#pragma unroll
    for (int i = 0; i < 8; i++)
#pragma unroll
        for (int j = 0; j < 4; j++) c[i][j] = 0ULL;

    for (int k = 0; k < 128; k++) {
        float a[8];
#pragma unroll
        for (int i = 0; i < 8; i++) a[i] = sA[(rb + i) * SA_STRIDE + k];
        ulonglong2 b01 = *(const ulonglong2*)&sB[k * FF + gb];
        ulonglong2 b23 = *(const ulonglong2*)&sB[k * FF + gb + 4];
        unsigned long long bb[4] = {b01.x, b01.y, b23.x, b23.y};
#pragma unroll
        for (int i = 0; i < 8; i++) {
            unsigned long long aa = pack2(a[i]);
#pragma unroll
            for (int j = 0; j < 4; j++) c[i][j] = ffma2(aa, bb[j], c[i][j]);
        }
    }

    // epilogue: scale row by dnorm, write scratch
#pragma unroll
    for (int i = 0; i < 8; i++) {
        int r = r0 + rb + i;
        float d = g_dnorm[r];
        float* o = g_xw + (size_t)r * FF + gb;
#pragma unroll
        for (int j = 0; j < 4; j++) {
            float2 v = *(float2*)&c[i][j];
            v.x *= d; v.y *= d;
            *(float2*)&o[j * 2] = v;
        }
    }
}

// ---------------- Kernel 3: out = relu(dnorm ⊙ (adj @ xw) + bias) ----------------
// block: (batch, row-tile of 128) -> 128x128 output, k-loop over 512 in 128 chunks
__global__ __launch_bounds__(256, 1)
void agg_kernel(const float* __restrict__ adj, const float* __restrict__ bias,
                float* __restrict__ out) {
    extern __shared__ float smem[];
    float* sA = smem;                       // [128][SA_STRIDE] adj rows x k-chunk
    float* sB = smem + 128 * SA_STRIDE;     // [128][128] xw k-chunk x g

    int tid   = threadIdx.x;
    int bId   = blockIdx.x;                 // 0..511
    int batch = bId >> 2;
    int r0    = (bId & 3) * 128;

    const float* A  = adj + (size_t)batch * NN * NN;
    const float* Bm = g_xw + (size_t)batch * NN * FF;

    int tx = tid & 15, ty = tid >> 4;
    int rb = ty * 8, gb = tx * 8;
    unsigned long long c[8][4];
#pragma unroll
    for (int i = 0; i < 8; i++)
#pragma unroll
        for (int j = 0; j < 4; j++) c[i][j] = 0ULL;

    for (int kt = 0; kt < 4; kt++) {
        int k0 = kt * 128;
        // load adj tile [128 rows][128 k] and xw tile [128 k][128 g]
#pragma unroll
        for (int i = 0; i < 16; i++) {
            int f   = tid + i * 256;
            int row = f >> 5, kq = f & 31;
            float4 va = *(const float4*)(A + (size_t)(r0 + row) * NN + k0 + kq * 4);
            *(float4*)&sA[row * SA_STRIDE + kq * 4] = va;
            float4 vb = *(const float4*)(Bm + (size_t)(k0 + row) * FF + kq * 4);
            *(float4*)&sB[f * 4] = vb;
        }
        __syncthreads();

        for (int k = 0; k < 128; k++) {
            float a[8];
#pragma unroll
            for (int i = 0; i < 8; i++) a[i] = sA[(rb + i) * SA_STRIDE + k];
            ulonglong2 b01 = *(const ulonglong2*)&sB[k * FF + gb];
            ulonglong2 b23 = *(const ulonglong2*)&sB[k * FF + gb + 4];
            unsigned long long bb[4] = {b01.x, b01.y, b23.x, b23.y};
#pragma unroll
            for (int i = 0; i < 8; i++) {
                unsigned long long aa = pack2(a[i]);
#pragma unroll
                for (int j = 0; j < 4; j++) c[i][j] = ffma2(aa, bb[j], c[i][j]);
            }
        }
        __syncthreads();
    }

    // epilogue: dnorm row-scale + bias + relu
#pragma unroll
    for (int i = 0; i < 8; i++) {
        int n = r0 + rb + i;
        float d = g_dnorm[batch * NN + n];
        float* o = out + (size_t)batch * NN * FF + (size_t)n * FF + gb;
#pragma unroll
        for (int j = 0; j < 4; j++) {
            float2 v = *(float2*)&c[i][j];
            float y0 = fmaxf(d * v.x + bias[gb + j * 2 + 0], 0.f);
            float y1 = fmaxf(d * v.y + bias[gb + j * 2 + 1], 0.f);
            *(float2*)&o[j * 2] = make_float2(y0, y1);
        }
    }
}

extern "C" void kernel_launch(void* const* d_in, const int* in_sizes, int n_in,
                              void* d_out, int out_size) {
    const float* adj  = (const float*)d_in[0];
    const float* x    = (const float*)d_in[1];
    const float* W    = (const float*)d_in[2];
    const float* bias = (const float*)d_in[3];
    float* out = (float*)d_out;

    // idempotent, not a stream op — safe under graph capture
    cudaFuncSetAttribute(xw_kernel, cudaFuncAttributeMaxDynamicSharedMemorySize, SMEM_BYTES);
    cudaFuncSetAttribute(agg_kernel, cudaFuncAttributeMaxDynamicSharedMemorySize, SMEM_BYTES);

    deg_kernel<<<(BB * NN) / 8, 256>>>(adj);
    xw_kernel<<<(BB * NN) / 128, 256, SMEM_BYTES>>>(x, W);
    agg_kernel<<<BB * 4, 256, SMEM_BYTES>>>(adj, bias, out);
}

// round 3
// speedup vs baseline: 1.8925x; 1.8925x over previous
#include <cuda_runtime.h>
#include <cuda_bf16.h>
#include <cstdint>

#define BB 128
#define NN 512
#define FF 128

// ---------------- device scratch (allocation-free rule) ----------------
__device__ __align__(256) __nv_bfloat16 g_hT_hi[(size_t)BB * FF * NN];
__device__ __align__(256) __nv_bfloat16 g_hT_lo[(size_t)BB * FF * NN];
__device__ __align__(256) __nv_bfloat16 g_WT_hi[FF * FF];
__device__ __align__(256) __nv_bfloat16 g_WT_lo[FF * FF];
__device__ float g_dnorm[BB * NN];

// ---------------- helpers ----------------
__device__ __forceinline__ uint32_t smem_u32(const void* p) {
    uint32_t r;
    asm("{ .reg .u64 t; cvta.to.shared.u64 t, %1; cvt.u32.u64 %0, t; }" : "=r"(r) : "l"(p));
    return r;
}
__device__ __forceinline__ void cp16(uint32_t dst, const void* src) {
    asm volatile("cp.async.cg.shared.global [%0], [%1], 16;" :: "r"(dst), "l"(src));
}
#define CP_COMMIT() asm volatile("cp.async.commit_group;" ::: "memory")
#define CP_WAIT_1() asm volatile("cp.async.wait_group 1;" ::: "memory")
#define CP_WAIT_0() asm volatile("cp.async.wait_group 0;" ::: "memory")

__device__ __forceinline__ void ldsm4(uint32_t r[4], uint32_t addr) {
    asm volatile("ldmatrix.sync.aligned.m8n8.x4.shared.b16 {%0,%1,%2,%3}, [%4];"
                 : "=r"(r[0]), "=r"(r[1]), "=r"(r[2]), "=r"(r[3]) : "r"(addr));
}
__device__ __forceinline__ void mma16816(float c[4], const uint32_t a[4],
                                         uint32_t b0, uint32_t b1) {
    asm volatile(
        "mma.sync.aligned.m16n8k16.row.col.f32.bf16.bf16.f32 "
        "{%0,%1,%2,%3}, {%4,%5,%6,%7}, {%8,%9}, {%0,%1,%2,%3};"
        : "+f"(c[0]), "+f"(c[1]), "+f"(c[2]), "+f"(c[3])
        : "r"(a[0]), "r"(a[1]), "r"(a[2]), "r"(a[3]), "r"(b0), "r"(b1));
}
__device__ __forceinline__ uint32_t pack2bf(float a, float b) {
    __nv_bfloat162 t;
    t.x = __float2bfloat16(a);
    t.y = __float2bfloat16(b);
    return *reinterpret_cast<uint32_t*>(&t);
}
__device__ __forceinline__ void split_bf16(float v, __nv_bfloat16& h, float& rem) {
    h = __float2bfloat16(v);
    rem = v - __bfloat162float(h);
}

// ---------------- Kernel 1: degree -> dnorm ----------------
__global__ void deg_kernel(const float* __restrict__ adj) {
    int row  = blockIdx.x * 8 + (threadIdx.x >> 5);
    int lane = threadIdx.x & 31;
    const float4* p = (const float4*)(adj + (size_t)row * NN);
    float s = 0.f;
#pragma unroll
    for (int i = 0; i < 4; i++) {
        float4 v = p[lane + i * 32];
        s += (v.x + v.y) + (v.z + v.w);
    }
#pragma unroll
    for (int o = 16; o; o >>= 1) s += __shfl_xor_sync(0xffffffffu, s, o);
    if (lane == 0) g_dnorm[row] = (s > 0.f) ? rsqrtf(s) : 0.f;
}

// ---------------- Kernel 2: W -> W^T (hi, lo) bf16 ----------------
__global__ void prep_w_kernel(const float* __restrict__ W) {
    int g = threadIdx.x;  // 128 threads
    __nv_bfloat162* oh = (__nv_bfloat162*)(g_WT_hi + g * FF);
    __nv_bfloat162* ol = (__nv_bfloat162*)(g_WT_lo + g * FF);
#pragma unroll 4
    for (int f = 0; f < FF; f += 2) {
        float v0 = W[f * FF + g], v1 = W[(f + 1) * FF + g];
        __nv_bfloat16 h0, h1; float r0, r1;
        split_bf16(v0, h0, r0); split_bf16(v1, h1, r1);
        __nv_bfloat162 ph; ph.x = h0; ph.y = h1;
        __nv_bfloat162 pl; pl.x = __float2bfloat16(r0); pl.y = __float2bfloat16(r1);
        oh[f >> 1] = ph; ol[f >> 1] = pl;
    }
}

// ---------------- Kernel 3: h^T = (dnorm ⊙ x)^T  (hi, lo) bf16 ----------------
__global__ __launch_bounds__(256) void prep_h_kernel(const float* __restrict__ x) {
    __shared__ float s[64 * 132];
    int b  = blockIdx.x >> 3;
    int k0 = (blockIdx.x & 7) * 64;
    int tid = threadIdx.x;
    const float4* gx = (const float4*)(x + ((size_t)b * NN + k0) * FF);
#pragma unroll
    for (int i = 0; i < 8; i++) {
        int f = tid + i * 256;           // float4 idx in 64x128 tile
        int k = f >> 5, g4 = (f & 31) * 4;
        float4 v = gx[f];
        float dn = g_dnorm[b * NN + k0 + k];
        s[k * 132 + g4 + 0] = v.x * dn;
        s[k * 132 + g4 + 1] = v.y * dn;
        s[k * 132 + g4 + 2] = v.z * dn;
        s[k * 132 + g4 + 3] = v.w * dn;
    }
    __syncthreads();
    int g = tid >> 1, half = tid & 1;
    __nv_bfloat162* oh = (__nv_bfloat162*)(g_hT_hi + ((size_t)b * FF + g) * NN + k0 + half * 32);
    __nv_bfloat162* ol = (__nv_bfloat162*)(g_hT_lo + ((size_t)b * FF + g) * NN + k0 + half * 32);
#pragma unroll
    for (int i = 0; i < 16; i++) {
        float v0 = s[(half * 32 + 2 * i + 0) * 132 + g];
        float v1 = s[(half * 32 + 2 * i + 1) * 132 + g];
        __nv_bfloat16 h0, h1; float r0, r1;
        split_bf16(v0, h0, r0); split_bf16(v1, h1, r1);
        __nv_bfloat162 ph; ph.x = h0; ph.y = h1;
        __nv_bfloat162 pl; pl.x = __float2bfloat16(r0); pl.y = __float2bfloat16(r1);
        oh[i] = ph; ol[i] = pl;
    }
}

// ---------------- Fused kernel: t = adj@h (K=512), out = relu(dn*(t@W)+b) ----------------
// smem map (bytes from base):
//   [0, 65536):    fp32 adj staging F[0]=+0, F[1]=+32768 ; later W tiles:
//                  Whi_a=+0, Whi_b=+16384, Wlo_a=+32768, Wlo_b=+49152
//   [65536, ...):  stage buf i at 65536 + i*65536: AH+0, AL+16384, BH+32768, BL+49152
//   A2 (t bf16) reuses buf0: A2hi_a/+16384 A2hi_b/+32768 A2lo_a/+49152 A2lo_b
#define FUSED_SMEM 196608
#define ST_BASE 65536

__global__ __launch_bounds__(256, 1)
void fused_kernel(const float* __restrict__ adj, const float* __restrict__ bias,
                  float* __restrict__ out) {
    extern __shared__ char sm[];
    uint32_t sbu = smem_u32(sm);
    int tid = threadIdx.x;
    int lane = tid & 31, wid = tid >> 5;
    int warp_m = wid & 1, warp_n = wid >> 1;     // 2 x 4 warps, warp tile 64x32
    int bb = blockIdx.x >> 2;
    int m0 = (blockIdx.x & 3) * 128;

    // ---- per-lane ldmatrix bases ----
    int rA = warp_m * 64 + ((lane >> 3) & 1) * 8 + (lane & 7);
    uint32_t arow = rA * 128, maskA = (rA & 7) << 4;
    uint32_t klA = (lane >> 4) * 16;
    int rB = warp_n * 32 + ((lane >> 4) & 1) * 8 + (lane & 7);
    uint32_t brow = rB * 128, maskB = (rB & 7) << 4;
    uint32_t klB = ((lane >> 3) & 1) * 16;

    // ---- load issuers ----
    auto load_stage = [&](int s) {
        int buf = s & 1;
        uint32_t Fd = sbu + buf * 32768;
        uint32_t BH = sbu + ST_BASE + buf * 65536 + 32768;
        uint32_t BL = BH + 16384;
        const char* asrc = (const char*)adj;
#pragma unroll
        for (int i = 0; i < 8; i++) {            // adj fp32: 128 rows x 64 k
            int c = tid + i * 256;               // 0..2047
            int row = c >> 4, ch = c & 15;
            cp16(Fd + row * 256 + ch * 16,
                 asrc + ((size_t)((bb * NN + m0 + row) * NN + s * 64)) * 4 + ch * 16);
        }
        const char* bh = (const char*)g_hT_hi;
        const char* bl = (const char*)g_hT_lo;
#pragma unroll
        for (int i = 0; i < 4; i++) {            // hT bf16: 128 f x 64 k (hi)
            int c = tid + i * 256;               // 0..1023
            int f = c >> 3, ch = c & 7;
            uint32_t so = f * 128 + ((ch * 16) ^ ((f & 7) << 4));
            size_t src = ((size_t)(bb * FF + f) * NN + s * 64) * 2 + ch * 16;
            cp16(BH + so, bh + src);
            cp16(BL + so, bl + src);
        }
    };
    auto load_W = [&]() {
        const char* wh = (const char*)g_WT_hi;
        const char* wl = (const char*)g_WT_lo;
#pragma unroll
        for (int i = 0; i < 4; i++) {
            int c = tid + i * 256;               // 0..1023
            int g = c >> 3, ch = c & 7;
            uint32_t so = g * 128 + ((ch * 16) ^ ((g & 7) << 4));
            cp16(sbu + so,         wh + g * 256 + ch * 16);        // hi half a
            cp16(sbu + 16384 + so, wh + g * 256 + 128 + ch * 16);  // hi half b
            cp16(sbu + 32768 + so, wl + g * 256 + ch * 16);        // lo half a
            cp16(sbu + 49152 + so, wl + g * 256 + 128 + ch * 16);  // lo half b
        }
    };

    // ---- prologue ----
    load_stage(0); CP_COMMIT();
    load_stage(1); CP_COMMIT();

    float C1[4][4][4];
#pragma unroll
    for (int i = 0; i < 4; i++)
#pragma unroll
        for (int j = 0; j < 4; j++)
#pragma unroll
            for (int k = 0; k < 4; k++) C1[i][j][k] = 0.f;

    int crow = tid >> 1, chalf = tid & 1;        // convert assignment

    for (int s = 0; s < 8; s++) {
        if (s < 7) { CP_WAIT_1(); } else { CP_WAIT_0(); }
        __syncthreads();

        int buf = s & 1;
        // ---- convert adj fp32 -> bf16 hi/lo (swizzled) ----
        {
            uint32_t Fd = sbu + buf * 32768;
            uint32_t AH = sbu + ST_BASE + buf * 65536;
            uint32_t AL = AH + 16384;
            uint32_t rbase = crow * 128, cmask = (crow & 7) << 4;
#pragma unroll
            for (int i = 0; i < 8; i++) {
                float4 v = *(float4*)(sm + (buf * 32768 + crow * 256 + chalf * 128 + i * 16));
                int k = chalf * 32 + i * 4;
                __nv_bfloat16 h0, h1, h2, h3; float r0, r1, r2, r3;
                split_bf16(v.x, h0, r0); split_bf16(v.y, h1, r1);
                split_bf16(v.z, h2, r2); split_bf16(v.w, h3, r3);
                uint2 hh, ll;
                __nv_bfloat162 p01, p23;
                p01.x = h0; p01.y = h1; p23.x = h2; p23.y = h3;
                hh.x = *reinterpret_cast<uint32_t*>(&p01);
                hh.y = *reinterpret_cast<uint32_t*>(&p23);
                ll.x = pack2bf(r0, r1);
                ll.y = pack2bf(r2, r3);
                uint32_t off = rbase + ((uint32_t)(k * 2) ^ cmask);
                *(uint2*)(sm + (AH - sbu) + off) = hh;
                *(uint2*)(sm + (AL - sbu) + off) = ll;
            }
        }
        __syncthreads();

        if (s == 7) { load_W(); CP_COMMIT(); }

        // ---- phase-1 MMAs on this stage ----
        {
            uint32_t AH = sbu + ST_BASE + buf * 65536;
            uint32_t AL = AH + 16384;
            uint32_t BH = AH + 32768;
            uint32_t BL = AH + 49152;
#pragma unroll
            for (int k16 = 0; k16 < 4; k16++) {
                uint32_t cba = (uint32_t)(k16 * 32 + klA) ^ maskA;
                uint32_t cbb = (uint32_t)(k16 * 32 + klB) ^ maskB;
                uint32_t ah[4][4], al[4][4], bh[2][4], bl[2][4];
#pragma unroll
                for (int i = 0; i < 4; i++) {
                    ldsm4(ah[i], AH + arow + i * 2048 + cba);
                    ldsm4(al[i], AL + arow + i * 2048 + cba);
                }
                ldsm4(bh[0], BH + brow + cbb);
                ldsm4(bh[1], BH + brow + 2048 + cbb);
                ldsm4(bl[0], BL + brow + cbb);
                ldsm4(bl[1], BL + brow + 2048 + cbb);
#pragma unroll
                for (int i = 0; i < 4; i++)
#pragma unroll
                    for (int j = 0; j < 4; j++) {
                        int jj = j >> 1, rp = (j & 1) * 2;
                        mma16816(C1[i][j], ah[i], bh[jj][rp], bh[jj][rp + 1]);
                        mma16816(C1[i][j], ah[i], bl[jj][rp], bl[jj][rp + 1]);
                        mma16816(C1[i][j], al[i], bh[jj][rp], bh[jj][rp + 1]);
                    }
            }
        }
        __syncthreads();
        if (s + 2 < 8) { load_stage(s + 2); CP_COMMIT(); }
    }

    // ---- epilogue 1: C1 (= t tile) -> smem bf16 hi/lo (buf0 region) ----
    {
        uint32_t A2H = ST_BASE + (warp_n >> 1) * 16384;   // byte offset within sm
        uint32_t A2L = A2H + 32768;
        int fcb = ((warp_n * 32) & 63) * 2 + (lane & 3) * 4;   // byte col within half
#pragma unroll
        for (int i = 0; i < 4; i++) {
#pragma unroll
            for (int j = 0; j < 4; j++) {
                int r0 = warp_m * 64 + i * 16 + (lane >> 2);
                int r1 = r0 + 8;
                int cb = fcb + j * 16;
                float v0 = C1[i][j][0], v1 = C1[i][j][1];
                float v2 = C1[i][j][2], v3 = C1[i][j][3];
                __nv_bfloat16 h0, h1, h2, h3; float q0, q1, q2, q3;
                split_bf16(v0, h0, q0); split_bf16(v1, h1, q1);
                split_bf16(v2, h2, q2); split_bf16(v3, h3, q3);
                __nv_bfloat162 p01; p01.x = h0; p01.y = h1;
                __nv_bfloat162 p23; p23.x = h2; p23.y = h3;
                uint32_t o0 = r0 * 128 + ((uint32_t)cb ^ ((r0 & 7) << 4));
                uint32_t o1 = r1 * 128 + ((uint32_t)cb ^ ((r1 & 7) << 4));
                *(uint32_t*)(sm + A2H + o0) = *reinterpret_cast<uint32_t*>(&p01);
                *(uint32_t*)(sm + A2H + o1) = *reinterpret_cast<uint32_t*>(&p23);
                *(uint32_t*)(sm + A2L + o0) = pack2bf(q0, q1);
                *(uint32_t*)(sm + A2L + o1) = pack2bf(q2, q3);
            }
        }
    }
    CP_WAIT_0();          // W tiles
    __syncthreads();      // A2 + W visible to all

    // ---- phase 2: out = t @ W, K = 128 ----
    float C2[4][4][4];
#pragma unroll
    for (int i = 0; i < 4; i++)
#pragma unroll
        for (int j = 0; j < 4; j++)
#pragma unroll
            for (int k = 0; k < 4; k++) C2[i][j][k] = 0.f;

#pragma unroll
    for (int k16 = 0; k16 < 8; k16++) {
        int half = k16 >> 2;
        uint32_t A2H = sbu + ST_BASE + half * 16384;
        uint32_t A2L = A2H + 32768;
        uint32_t WH = sbu + half * 16384;
        uint32_t WL = WH + 32768;
        uint32_t cba = (uint32_t)((k16 & 3) * 32 + klA) ^ maskA;
        uint32_t cbb = (uint32_t)((k16 & 3) * 32 + klB) ^ maskB;
        uint32_t ah[4][4], al[4][4], bh[2][4], bl[2][4];
#pragma unroll
        for (int i = 0; i < 4; i++) {
            ldsm4(ah[i], A2H + arow + i * 2048 + cba);
            ldsm4(al[i], A2L + arow + i * 2048 + cba);
        }
        ldsm4(bh[0], WH + brow + cbb);
        ldsm4(bh[1], WH + brow + 2048 + cbb);
        ldsm4(bl[0], WL + brow + cbb);
        ldsm4(bl[1], WL + brow + 2048 + cbb);
#pragma unroll
        for (int i = 0; i < 4; i++)
#pragma unroll
            for (int j = 0; j < 4; j++) {
                int jj = j >> 1, rp = (j & 1) * 2;
                mma16816(C2[i][j], ah[i], bh[jj][rp], bh[jj][rp + 1]);
                mma16816(C2[i][j], ah[i], bl[jj][rp], bl[jj][rp + 1]);
                mma16816(C2[i][j], al[i], bh[jj][rp], bh[jj][rp + 1]);
            }
    }

    // ---- epilogue 2: relu(dnorm * acc + bias) -> out ----
#pragma unroll
    for (int i = 0; i < 4; i++) {
        int r0 = warp_m * 64 + i * 16 + (lane >> 2);
        int node0 = m0 + r0, node1 = node0 + 8;
        float dn0 = g_dnorm[bb * NN + node0];
        float dn1 = g_dnorm[bb * NN + node1];
#pragma unroll
        for (int j = 0; j < 4; j++) {
            int g = warp_n * 32 + j * 8 + (lane & 3) * 2;
            float b0 = bias[g], b1 = bias[g + 1];
            float2 v0, v1;
            v0.x = fmaxf(dn0 * C2[i][j][0] + b0, 0.f);
            v0.y = fmaxf(dn0 * C2[i][j][1] + b1, 0.f);
            v1.x = fmaxf(dn1 * C2[i][j][2] + b0, 0.f);
            v1.y = fmaxf(dn1 * C2[i][j][3] + b1, 0.f);
            *(float2*)(out + ((size_t)(bb * NN + node0)) * FF + g) = v0;
            *(float2*)(out + ((size_t)(bb * NN + node1)) * FF + g) = v1;
        }
    }
}

// ---------------- launch ----------------
extern "C" void kernel_launch(void* const* d_in, const int* in_sizes, int n_in,
                              void* d_out, int out_size) {
    const float* adj  = (const float*)d_in[0];
    const float* x    = (const float*)d_in[1];
    const float* W    = (const float*)d_in[2];
    const float* bias = (const float*)d_in[3];
    float* out = (float*)d_out;

    cudaFuncSetAttribute(fused_kernel, cudaFuncAttributeMaxDynamicSharedMemorySize,
                         FUSED_SMEM);

    deg_kernel<<<(BB * NN) / 8, 256>>>(adj);
    prep_w_kernel<<<1, 128>>>(W);
    prep_h_kernel<<<BB * 8, 256>>>(x);
    fused_kernel<<<BB * 4, 256, FUSED_SMEM>>>(adj, bias, out);
}

// round 10
// speedup vs baseline: 2.2738x; 1.2015x over previous
#include <cuda_runtime.h>
#include <cuda_bf16.h>
#include <cstdint>

#define BB 128
#define NN 512
#define FF 128

// ---------------- device scratch (allocation-free rule) ----------------
__device__ __align__(256) float g_hT[(size_t)BB * FF * NN];  // tf32-rounded (dnorm*x)^T
__device__ __align__(256) float g_WT[FF * FF];               // tf32-rounded W^T
__device__ float g_dnorm[BB * NN];

// ---------------- helpers ----------------
__device__ __forceinline__ uint32_t smem_u32(const void* p) {
    uint32_t r;
    asm("{ .reg .u64 t; cvta.to.shared.u64 t, %1; cvt.u32.u64 %0, t; }" : "=r"(r) : "l"(p));
    return r;
}
__device__ __forceinline__ void cp16(uint32_t dst, const void* src) {
    asm volatile("cp.async.cg.shared.global [%0], [%1], 16;" :: "r"(dst), "l"(src));
}
#define CP_COMMIT() asm volatile("cp.async.commit_group;" ::: "memory")
#define CP_WAIT_2() asm volatile("cp.async.wait_group 2;" ::: "memory")
#define CP_WAIT_1() asm volatile("cp.async.wait_group 1;" ::: "memory")
#define CP_WAIT_0() asm volatile("cp.async.wait_group 0;" ::: "memory")

__device__ __forceinline__ uint32_t lds32(uint32_t a) {
    uint32_t v;
    asm volatile("ld.shared.b32 %0, [%1];" : "=r"(v) : "r"(a));
    return v;
}
__device__ __forceinline__ void sts64(uint32_t a, float x, float y) {
    asm volatile("st.shared.v2.f32 [%0], {%1, %2};" :: "r"(a), "f"(x), "f"(y));
}
__device__ __forceinline__ uint32_t rna(uint32_t x) {
    uint32_t y;
    asm("cvt.rna.tf32.f32 %0, %1;" : "=r"(y) : "r"(x));
    return y;
}
__device__ __forceinline__ float rna_f(float v) {
    return __uint_as_float(rna(__float_as_uint(v)));
}
__device__ __forceinline__ void mma_tf32(float c[4], const uint32_t a[4],
                                         uint32_t b0, uint32_t b1) {
    asm volatile(
        "mma.sync.aligned.m16n8k8.row.col.f32.tf32.tf32.f32 "
        "{%0,%1,%2,%3}, {%4,%5,%6,%7}, {%8,%9}, {%0,%1,%2,%3};"
        : "+f"(c[0]), "+f"(c[1]), "+f"(c[2]), "+f"(c[3])
        : "r"(a[0]), "r"(a[1]), "r"(a[2]), "r"(a[3]), "r"(b0), "r"(b1));
}

// ---------------- Kernel 1: degree -> dnorm ----------------
__global__ void deg_kernel(const float* __restrict__ adj) {
    int row  = blockIdx.x * 8 + (threadIdx.x >> 5);
    int lane = threadIdx.x & 31;
    const float4* p = (const float4*)(adj + (size_t)row * NN);
    float s = 0.f;
#pragma unroll
    for (int i = 0; i < 4; i++) {
        float4 v = p[lane + i * 32];
        s += (v.x + v.y) + (v.z + v.w);
    }
#pragma unroll
    for (int o = 16; o; o >>= 1) s += __shfl_xor_sync(0xffffffffu, s, o);
    if (lane == 0) g_dnorm[row] = (s > 0.f) ? rsqrtf(s) : 0.f;
}

// ---------------- Kernel 2: W -> W^T, tf32-rounded ----------------
__global__ void prep_w_kernel(const float* __restrict__ W) {
    int g = threadIdx.x;  // 128 threads
    float2* o = (float2*)(g_WT + g * FF);
#pragma unroll 4
    for (int f = 0; f < FF; f += 2) {
        float2 v;
        v.x = rna_f(W[f * FF + g]);
        v.y = rna_f(W[(f + 1) * FF + g]);
        o[f >> 1] = v;
    }
}

// ---------------- Kernel 3: h^T = (dnorm ⊙ x)^T, tf32-rounded ----------------
__global__ __launch_bounds__(256) void prep_h_kernel(const float* __restrict__ x) {
    __shared__ float s[64 * 132];
    int b  = blockIdx.x >> 3;
    int k0 = (blockIdx.x & 7) * 64;
    int tid = threadIdx.x;
    const float4* gx = (const float4*)(x + ((size_t)b * NN + k0) * FF);
#pragma unroll
    for (int i = 0; i < 8; i++) {
        int f = tid + i * 256;           // float4 idx in 64x128 tile
        int k = f >> 5, g4 = (f & 31) * 4;
        float4 v = gx[f];
        float dn = g_dnorm[b * NN + k0 + k];
        s[k * 132 + g4 + 0] = v.x * dn;
        s[k * 132 + g4 + 1] = v.y * dn;
        s[k * 132 + g4 + 2] = v.z * dn;
        s[k * 132 + g4 + 3] = v.w * dn;
    }
    __syncthreads();
    int g = tid >> 1, half = tid & 1;
    float2* oh = (float2*)(g_hT + ((size_t)b * FF + g) * NN + k0 + half * 32);
#pragma unroll
    for (int i = 0; i < 16; i++) {
        float2 v;
        v.x = rna_f(s[(half * 32 + 2 * i + 0) * 132 + g]);
        v.y = rna_f(s[(half * 32 + 2 * i + 1) * 132 + g]);
        oh[i] = v;
    }
}

// ---------------- Fused: t = adj@h (tf32, K=512); out = relu(dn*(t@W)+b) ----------------
// 512 threads, warp grid 4x4, warp tile 32x32, per-thread C[2][4][4].
// smem phase 1: 3 stages x 36864 B: A[128r x 32k, stride 144B] + B[128f x 32k, stride 144B]
// smem phase 2: A2 (t fp32) at 0, stride 528B (67584 B);
//               W at 67584: half h at +h*34816 (128 rows x 272B), both halves resident.
// FUSED_SMEM = max(3*36864, 67584 + 2*34816) = 137216.
#define STG 36864
#define BOFF 18432
#define ASTRIDE 144
#define A2STRIDE 528
#define WSTRIDE 272
#define WOFF 67584
#define WHALF 34816
#define FUSED_SMEM 137216

__global__ __launch_bounds__(512)
void fused_kernel(const float* __restrict__ adj, const float* __restrict__ bias,
                  float* __restrict__ out) {
    extern __shared__ char sm[];
    uint32_t sbu = smem_u32(sm);
    int tid = threadIdx.x, lane = tid & 31, wid = tid >> 5;
    int warp_m = wid & 3, warp_n = wid >> 2;   // 4 x 4 warps, warp tile 32x32
    int gid = lane >> 2, tq = lane & 3;
    int bb = blockIdx.x >> 2, m0 = (blockIdx.x & 3) * 128;

    const char* adjb = (const char*)adj;
    const char* hb = (const char*)g_hT;
    const char* wb = (const char*)g_WT;

    auto load_stage = [&](int s) {
        uint32_t base = sbu + (s % 3) * STG;
#pragma unroll
        for (int i = 0; i < 2; i++) {                 // adj: 128 rows x 32 floats
            int c = tid + i * 512;                    // 0..1023
            int row = c >> 3, ch = c & 7;
            cp16(base + row * ASTRIDE + ch * 16,
                 adjb + ((size_t)(bb * NN + m0 + row) * NN + s * 32) * 4 + ch * 16);
        }
#pragma unroll
        for (int i = 0; i < 2; i++) {                 // hT: 128 f x 32 k
            int c = tid + i * 512;
            int f = c >> 3, ch = c & 7;
            cp16(base + BOFF + f * ASTRIDE + ch * 16,
                 hb + ((size_t)(bb * FF + f) * NN + s * 32) * 4 + ch * 16);
        }
    };

    float C[2][4][4];
#pragma unroll
    for (int i = 0; i < 2; i++)
#pragma unroll
        for (int j = 0; j < 4; j++)
#pragma unroll
            for (int k = 0; k < 4; k++) C[i][j][k] = 0.f;

    load_stage(0); CP_COMMIT();
    load_stage(1); CP_COMMIT();
    load_stage(2); CP_COMMIT();

    for (int s = 0; s < 16; s++) {
        if (s < 14) { CP_WAIT_2(); } else if (s == 14) { CP_WAIT_1(); } else { CP_WAIT_0(); }
        __syncthreads();
        uint32_t base = sbu + (s % 3) * STG;
#pragma unroll
        for (int k8 = 0; k8 < 4; k8++) {
            uint32_t b[4][2];
#pragma unroll
            for (int j = 0; j < 4; j++) {
                uint32_t ba = base + BOFF + (warp_n * 32 + j * 8 + gid) * ASTRIDE
                            + (k8 * 8 + tq) * 4;
                b[j][0] = lds32(ba);
                b[j][1] = lds32(ba + 16);
            }
            uint32_t a[2][4];
#pragma unroll
            for (int i = 0; i < 2; i++) {
                uint32_t aa = base + (warp_m * 32 + i * 16 + gid) * ASTRIDE
                            + (k8 * 8 + tq) * 4;
                a[i][0] = rna(lds32(aa));
                a[i][1] = rna(lds32(aa + 8 * ASTRIDE));
                a[i][2] = rna(lds32(aa + 16));
                a[i][3] = rna(lds32(aa + 8 * ASTRIDE + 16));
            }
#pragma unroll
            for (int i = 0; i < 2; i++)
#pragma unroll
                for (int j = 0; j < 4; j++)
                    mma_tf32(C[i][j], a[i], b[j][0], b[j][1]);
        }
        __syncthreads();
        if (s + 3 < 16) { load_stage(s + 3); CP_COMMIT(); }
    }

    // ---- prefetch W (both halves resident; 128 rows x 256B each, stride 272B) ----
#pragma unroll
    for (int i = 0; i < 8; i++) {
        int c = tid + i * 512;                        // 0..4095 (16B chunks, 64 KB total)
        int half = c >> 11;                           // 0..1 (k-half)
        int r = c & 2047;
        int g = r >> 4, ch = r & 15;                  // g row (0..127), chunk (0..15)
        cp16(sbu + WOFF + half * WHALF + g * WSTRIDE + ch * 16,
             wb + ((size_t)g * FF + half * 64) * 4 + ch * 16);
    }
    CP_COMMIT();

    // ---- epilogue 1: C (= t tile) -> smem fp32 A2; zero C for phase 2 ----
#pragma unroll
    for (int i = 0; i < 2; i++) {
        int r0 = warp_m * 32 + i * 16 + gid;
#pragma unroll
        for (int j = 0; j < 4; j++) {
            int cc = warp_n * 32 + j * 8 + tq * 2;
            sts64(sbu + r0 * A2STRIDE + cc * 4, C[i][j][0], C[i][j][1]);
            sts64(sbu + (r0 + 8) * A2STRIDE + cc * 4, C[i][j][2], C[i][j][3]);
            C[i][j][0] = C[i][j][1] = C[i][j][2] = C[i][j][3] = 0.f;
        }
    }
    CP_WAIT_0();
    __syncthreads();

    // ---- phase 2: out = t @ W (K = 128) ----
#pragma unroll
    for (int k8 = 0; k8 < 16; k8++) {
        int half = k8 >> 3;
        uint32_t b[4][2];
#pragma unroll
        for (int j = 0; j < 4; j++) {
            uint32_t ba = sbu + WOFF + half * WHALF
                        + (warp_n * 32 + j * 8 + gid) * WSTRIDE
                        + ((k8 & 7) * 8 + tq) * 4;
            b[j][0] = lds32(ba);
            b[j][1] = lds32(ba + 16);
        }
        uint32_t a[2][4];
#pragma unroll
        for (int i = 0; i < 2; i++) {
            uint32_t aa = sbu + (warp_m * 32 + i * 16 + gid) * A2STRIDE
                        + (k8 * 8 + tq) * 4;
            a[i][0] = rna(lds32(aa));
            a[i][1] = rna(lds32(aa + 8 * A2STRIDE));
            a[i][2] = rna(lds32(aa + 16));
            a[i][3] = rna(lds32(aa + 8 * A2STRIDE + 16));
        }
#pragma unroll
        for (int i = 0; i < 2; i++)
#pragma unroll
            for (int j = 0; j < 4; j++)
                mma_tf32(C[i][j], a[i], b[j][0], b[j][1]);
    }

    // ---- epilogue 2: relu(dnorm * acc + bias) -> out ----
#pragma unroll
    for (int i = 0; i < 2; i++) {
        int r0 = warp_m * 32 + i * 16 + gid;
        int node0 = m0 + r0, node1 = node0 + 8;
        float dn0 = g_dnorm[bb * NN + node0];
        float dn1 = g_dnorm[bb * NN + node1];
#pragma unroll
        for (int j = 0; j < 4; j++) {
            int g = warp_n * 32 + j * 8 + tq * 2;
            float b0 = bias[g], b1 = bias[g + 1];
            float2 v0, v1;
            v0.x = fmaxf(dn0 * C[i][j][0] + b0, 0.f);
            v0.y = fmaxf(dn0 * C[i][j][1] + b1, 0.f);
            v1.x = fmaxf(dn1 * C[i][j][2] + b0, 0.f);
            v1.y = fmaxf(dn1 * C[i][j][3] + b1, 0.f);
            *(float2*)(out + ((size_t)(bb * NN + node0)) * FF + g) = v0;
            *(float2*)(out + ((size_t)(bb * NN + node1)) * FF + g) = v1;
        }
    }
}

// ---------------- launch ----------------
extern "C" void kernel_launch(void* const* d_in, const int* in_sizes, int n_in,
                              void* d_out, int out_size) {
    const float* adj  = (const float*)d_in[0];
    const float* x    = (const float*)d_in[1];
    const float* W    = (const float*)d_in[2];
    const float* bias = (const float*)d_in[3];
    float* out = (float*)d_out;

    cudaFuncSetAttribute(fused_kernel, cudaFuncAttributeMaxDynamicSharedMemorySize,
                         FUSED_SMEM);

    deg_kernel<<<(BB * NN) / 8, 256>>>(adj);
    prep_w_kernel<<<1, 128>>>(W);
    prep_h_kernel<<<BB * 8, 256>>>(x);
    fused_kernel<<<BB * 4, 512, FUSED_SMEM>>>(adj, bias, out);
}

// round 11
// speedup vs baseline: 2.4384x; 1.0724x over previous
#include <cuda_runtime.h>
#include <cuda_bf16.h>
#include <cstdint>

#define BB 128
#define NN 512
#define FF 128

// ---------------- device scratch (allocation-free rule) ----------------
__device__ __align__(256) float g_hT[(size_t)BB * FF * NN];  // tf32-rounded (dnorm*x)^T
__device__ __align__(256) float g_WT[FF * FF];               // tf32-rounded W^T
__device__ float g_dnorm[BB * NN];

// ---------------- helpers ----------------
__device__ __forceinline__ uint32_t smem_u32(const void* p) {
    uint32_t r;
    asm("{ .reg .u64 t; cvta.to.shared.u64 t, %1; cvt.u32.u64 %0, t; }" : "=r"(r) : "l"(p));
    return r;
}
__device__ __forceinline__ void cp16(uint32_t dst, const void* src) {
    asm volatile("cp.async.cg.shared.global [%0], [%1], 16;" :: "r"(dst), "l"(src));
}
#define CP_COMMIT() asm volatile("cp.async.commit_group;" ::: "memory")
#define CP_WAIT_2() asm volatile("cp.async.wait_group 2;" ::: "memory")
#define CP_WAIT_1() asm volatile("cp.async.wait_group 1;" ::: "memory")
#define CP_WAIT_0() asm volatile("cp.async.wait_group 0;" ::: "memory")

__device__ __forceinline__ uint32_t lds32(uint32_t a) {
    uint32_t v;
    asm volatile("ld.shared.b32 %0, [%1];" : "=r"(v) : "r"(a));
    return v;
}
__device__ __forceinline__ void sts64(uint32_t a, float x, float y) {
    asm volatile("st.shared.v2.f32 [%0], {%1, %2};" :: "r"(a), "f"(x), "f"(y));
}
__device__ __forceinline__ uint32_t rna(uint32_t x) {
    uint32_t y;
    asm("cvt.rna.tf32.f32 %0, %1;" : "=r"(y) : "r"(x));
    return y;
}
__device__ __forceinline__ float rna_f(float v) {
    return __uint_as_float(rna(__float_as_uint(v)));
}
__device__ __forceinline__ void mma_tf32(float c[4], const uint32_t a[4],
                                         uint32_t b0, uint32_t b1) {
    asm volatile(
        "mma.sync.aligned.m16n8k8.row.col.f32.tf32.tf32.f32 "
        "{%0,%1,%2,%3}, {%4,%5,%6,%7}, {%8,%9}, {%0,%1,%2,%3};"
        : "+f"(c[0]), "+f"(c[1]), "+f"(c[2]), "+f"(c[3])
        : "r"(a[0]), "r"(a[1]), "r"(a[2]), "r"(a[3]), "r"(b0), "r"(b1));
}

// ---------------- Kernel 1: degree -> dnorm ----------------
__global__ void deg_kernel(const float* __restrict__ adj) {
    int row  = blockIdx.x * 8 + (threadIdx.x >> 5);
    int lane = threadIdx.x & 31;
    const float4* p = (const float4*)(adj + (size_t)row * NN);
    float s = 0.f;
#pragma unroll
    for (int i = 0; i < 4; i++) {
        float4 v = p[lane + i * 32];
        s += (v.x + v.y) + (v.z + v.w);
    }
#pragma unroll
    for (int o = 16; o; o >>= 1) s += __shfl_xor_sync(0xffffffffu, s, o);
    if (lane == 0) g_dnorm[row] = (s > 0.f) ? rsqrtf(s) : 0.f;
}

// ---------------- Kernel 2: W -> W^T, tf32-rounded (parallel) ----------------
__global__ void prep_w_kernel(const float* __restrict__ W) {
    int idx = blockIdx.x * 256 + threadIdx.x;   // 64 blocks x 256 = 16384
    int f = idx >> 7, g = idx & 127;
    g_WT[g * FF + f] = rna_f(W[f * FF + g]);
}

// ---------------- Kernel 3: h^T = (dnorm ⊙ x)^T, tf32-rounded ----------------
__global__ __launch_bounds__(256) void prep_h_kernel(const float* __restrict__ x) {
    __shared__ float s[64 * 132];
    int b  = blockIdx.x >> 3;
    int k0 = (blockIdx.x & 7) * 64;
    int tid = threadIdx.x;
    const float4* gx = (const float4*)(x + ((size_t)b * NN + k0) * FF);
#pragma unroll
    for (int i = 0; i < 8; i++) {
        int f = tid + i * 256;           // float4 idx in 64x128 tile
        int k = f >> 5, g4 = (f & 31) * 4;
        float4 v = gx[f];
        float dn = g_dnorm[b * NN + k0 + k];
        s[k * 132 + g4 + 0] = v.x * dn;
        s[k * 132 + g4 + 1] = v.y * dn;
        s[k * 132 + g4 + 2] = v.z * dn;
        s[k * 132 + g4 + 3] = v.w * dn;
    }
    __syncthreads();
    int g = tid >> 1, half = tid & 1;
    float2* oh = (float2*)(g_hT + ((size_t)b * FF + g) * NN + k0 + half * 32);
#pragma unroll
    for (int i = 0; i < 16; i++) {
        float2 v;
        v.x = rna_f(s[(half * 32 + 2 * i + 0) * 132 + g]);
        v.y = rna_f(s[(half * 32 + 2 * i + 1) * 132 + g]);
        oh[i] = v;
    }
}

// ---------------- Fused: t = adj@h (tf32, K=512); out = relu(dn*(t@W)+b) ----------------
// 512 threads, __launch_bounds__(512, 2) -> 2 CTAs/SM (32 warps).
// smem phase 1: 3 stages x 36864 B: A[128r x 32k, stride 144B] + B[128f x 32k, stride 144B]
// smem phase 2: A2 (t fp32) at 0, stride 528B (67584 B);
//               W ONE half at 67584 (128 rows x 272B = 34816 B), reloaded mid-phase.
// FUSED_SMEM = 3*36864 = 110592 (phase 2 peak 102400 <= that). 2 x 110592 fits 228 KB.
#define STG 36864
#define BOFF 18432
#define ASTRIDE 144
#define A2STRIDE 528
#define WSTRIDE 272
#define WOFF 67584
#define FUSED_SMEM 110592

__global__ __launch_bounds__(512, 2)
void fused_kernel(const float* __restrict__ adj, const float* __restrict__ bias,
                  float* __restrict__ out) {
    extern __shared__ char sm[];
    uint32_t sbu = smem_u32(sm);
    int tid = threadIdx.x, lane = tid & 31, wid = tid >> 5;
    int warp_m = wid & 3, warp_n = wid >> 2;   // 4 x 4 warps, warp tile 32x32
    int gid = lane >> 2, tq = lane & 3;
    int bb = blockIdx.x >> 2, m0 = (blockIdx.x & 3) * 128;

    const char* adjb = (const char*)adj;
    const char* hb = (const char*)g_hT;
    const char* wb = (const char*)g_WT;

    auto load_stage = [&](int s) {
        uint32_t base = sbu + (s % 3) * STG;
#pragma unroll
        for (int i = 0; i < 2; i++) {                 // adj: 128 rows x 32 floats
            int c = tid + i * 512;                    // 0..1023
            int row = c >> 3, ch = c & 7;
            cp16(base + row * ASTRIDE + ch * 16,
                 adjb + ((size_t)(bb * NN + m0 + row) * NN + s * 32) * 4 + ch * 16);
        }
#pragma unroll
        for (int i = 0; i < 2; i++) {                 // hT: 128 f x 32 k
            int c = tid + i * 512;
            int f = c >> 3, ch = c & 7;
            cp16(base + BOFF + f * ASTRIDE + ch * 16,
                 hb + ((size_t)(bb * FF + f) * NN + s * 32) * 4 + ch * 16);
        }
    };
    auto load_w_half = [&](int half) {
#pragma unroll
        for (int i = 0; i < 4; i++) {
            int c = tid + i * 512;                    // 0..2047 (16B chunks, 32 KB)
            int g = c >> 4, ch = c & 15;              // g row (0..127), chunk (0..15)
            cp16(sbu + WOFF + g * WSTRIDE + ch * 16,
                 wb + ((size_t)g * FF + half * 64) * 4 + ch * 16);
        }
    };

    float C[2][4][4];
#pragma unroll
    for (int i = 0; i < 2; i++)
#pragma unroll
        for (int j = 0; j < 4; j++)
#pragma unroll
            for (int k = 0; k < 4; k++) C[i][j][k] = 0.f;

    load_stage(0); CP_COMMIT();
    load_stage(1); CP_COMMIT();
    load_stage(2); CP_COMMIT();

    for (int s = 0; s < 16; s++) {
        if (s < 14) { CP_WAIT_2(); } else if (s == 14) { CP_WAIT_1(); } else { CP_WAIT_0(); }
        __syncthreads();
        uint32_t base = sbu + (s % 3) * STG;
#pragma unroll
        for (int k8 = 0; k8 < 4; k8++) {
            uint32_t b[4][2];
#pragma unroll
            for (int j = 0; j < 4; j++) {
                uint32_t ba = base + BOFF + (warp_n * 32 + j * 8 + gid) * ASTRIDE
                            + (k8 * 8 + tq) * 4;
                b[j][0] = lds32(ba);
                b[j][1] = lds32(ba + 16);
            }
            uint32_t a[2][4];
#pragma unroll
            for (int i = 0; i < 2; i++) {
                uint32_t aa = base + (warp_m * 32 + i * 16 + gid) * ASTRIDE
                            + (k8 * 8 + tq) * 4;
                a[i][0] = rna(lds32(aa));
                a[i][1] = rna(lds32(aa + 8 * ASTRIDE));
                a[i][2] = rna(lds32(aa + 16));
                a[i][3] = rna(lds32(aa + 8 * ASTRIDE + 16));
            }
#pragma unroll
            for (int i = 0; i < 2; i++)
#pragma unroll
                for (int j = 0; j < 4; j++)
                    mma_tf32(C[i][j], a[i], b[j][0], b[j][1]);
        }
        __syncthreads();
        if (s + 3 < 16) { load_stage(s + 3); CP_COMMIT(); }
    }

    // ---- prefetch W half 0 (k cols 0..63 of W^T rows) ----
    load_w_half(0);
    CP_COMMIT();

    // ---- epilogue 1: C (= t tile) -> smem fp32 A2; zero C for phase 2 ----
#pragma unroll
    for (int i = 0; i < 2; i++) {
        int r0 = warp_m * 32 + i * 16 + gid;
#pragma unroll
        for (int j = 0; j < 4; j++) {
            int cc = warp_n * 32 + j * 8 + tq * 2;
            sts64(sbu + r0 * A2STRIDE + cc * 4, C[i][j][0], C[i][j][1]);
            sts64(sbu + (r0 + 8) * A2STRIDE + cc * 4, C[i][j][2], C[i][j][3]);
            C[i][j][0] = C[i][j][1] = C[i][j][2] = C[i][j][3] = 0.f;
        }
    }
    CP_WAIT_0();
    __syncthreads();

    // ---- phase 2: out = t @ W (K = 128, two k-halves; W reloaded between) ----
    auto mma_p2 = [&](int kb) {
#pragma unroll
        for (int k8 = 0; k8 < 8; k8++) {
            uint32_t b[4][2];
#pragma unroll
            for (int j = 0; j < 4; j++) {
                uint32_t ba = sbu + WOFF + (warp_n * 32 + j * 8 + gid) * WSTRIDE
                            + (k8 * 8 + tq) * 4;
                b[j][0] = lds32(ba);
                b[j][1] = lds32(ba + 16);
            }
            uint32_t a[2][4];
#pragma unroll
            for (int i = 0; i < 2; i++) {
                uint32_t aa = sbu + (warp_m * 32 + i * 16 + gid) * A2STRIDE
                            + (kb + k8 * 8 + tq) * 4;
                a[i][0] = rna(lds32(aa));
                a[i][1] = rna(lds32(aa + 8 * A2STRIDE));
                a[i][2] = rna(lds32(aa + 16));
                a[i][3] = rna(lds32(aa + 8 * A2STRIDE + 16));
            }
#pragma unroll
            for (int i = 0; i < 2; i++)
#pragma unroll
                for (int j = 0; j < 4; j++)
                    mma_tf32(C[i][j], a[i], b[j][0], b[j][1]);
        }
    };

    mma_p2(0);
    __syncthreads();                 // all warps done reading W half 0
    load_w_half(1);
    CP_COMMIT();
    CP_WAIT_0();
    __syncthreads();
    mma_p2(64);

    // ---- epilogue 2: relu(dnorm * acc + bias) -> out ----
#pragma unroll
    for (int i = 0; i < 2; i++) {
        int r0 = warp_m * 32 + i * 16 + gid;
        int node0 = m0 + r0, node1 = node0 + 8;
        float dn0 = g_dnorm[bb * NN + node0];
        float dn1 = g_dnorm[bb * NN + node1];
#pragma unroll
        for (int j = 0; j < 4; j++) {
            int g = warp_n * 32 + j * 8 + tq * 2;
            float b0 = bias[g], b1 = bias[g + 1];
            float2 v0, v1;
            v0.x = fmaxf(dn0 * C[i][j][0] + b0, 0.f);
            v0.y = fmaxf(dn0 * C[i][j][1] + b1, 0.f);
            v1.x = fmaxf(dn1 * C[i][j][2] + b0, 0.f);
            v1.y = fmaxf(dn1 * C[i][j][3] + b1, 0.f);
            *(float2*)(out + ((size_t)(bb * NN + node0)) * FF + g) = v0;
            *(float2*)(out + ((size_t)(bb * NN + node1)) * FF + g) = v1;
        }
    }
}

// ---------------- launch ----------------
extern "C" void kernel_launch(void* const* d_in, const int* in_sizes, int n_in,
                              void* d_out, int out_size) {
    const float* adj  = (const float*)d_in[0];
    const float* x    = (const float*)d_in[1];
    const float* W    = (const float*)d_in[2];
    const float* bias = (const float*)d_in[3];
    float* out = (float*)d_out;

    cudaFuncSetAttribute(fused_kernel, cudaFuncAttributeMaxDynamicSharedMemorySize,
                         FUSED_SMEM);

    deg_kernel<<<(BB * NN) / 8, 256>>>(adj);
    prep_w_kernel<<<64, 256>>>(W);
    prep_h_kernel<<<BB * 8, 256>>>(x);
    fused_kernel<<<BB * 4, 512, FUSED_SMEM>>>(adj, bias, out);
}

// round 16
// speedup vs baseline: 2.7482x; 1.1270x over previous
#include <cuda_runtime.h>
#include <cuda_bf16.h>
#include <cstdint>

#define BB 128
#define NN 512
#define FF 128

// ---------------- device scratch (allocation-free rule) ----------------
// frag-linear hT: [b][k8 0..63][jj 0..7][gid 0..7][tq 0..3] float4
//   float4 = { h[f0][k], h[f0][k+4], h[f1][k], h[f1][k+4] },
//   f0 = jj*16+gid, f1 = f0+8, k = k8*8+tq, h[f][k] = rna(x[b][k][f]*dnorm[b][k])
__device__ __align__(256) float4 g_hTf[(size_t)BB * 64 * 8 * 32];
// frag-linear W^T: [k8 0..15][jj 0..7][gid][tq] float4 (same formula, WT[n][k]=W[k][n])
__device__ __align__(256) float4 g_Wf[16 * 8 * 32];
__device__ float g_dnorm[BB * NN];

// ---------------- helpers ----------------
__device__ __forceinline__ uint32_t smem_u32(const void* p) {
    uint32_t r;
    asm("{ .reg .u64 t; cvta.to.shared.u64 t, %1; cvt.u32.u64 %0, t; }" : "=r"(r) : "l"(p));
    return r;
}
__device__ __forceinline__ void cp16(uint32_t dst, const void* src) {
    asm volatile("cp.async.cg.shared.global [%0], [%1], 16;" :: "r"(dst), "l"(src));
}
#define CP_COMMIT() asm volatile("cp.async.commit_group;" ::: "memory")
#define CP_WAIT_2() asm volatile("cp.async.wait_group 2;" ::: "memory")
#define CP_WAIT_1() asm volatile("cp.async.wait_group 1;" ::: "memory")
#define CP_WAIT_0() asm volatile("cp.async.wait_group 0;" ::: "memory")

__device__ __forceinline__ uint32_t lds32(uint32_t a) {
    uint32_t v;
    asm volatile("ld.shared.b32 %0, [%1];" : "=r"(v) : "r"(a));
    return v;
}
__device__ __forceinline__ void lds128(uint32_t r[4], uint32_t a) {
    asm volatile("ld.shared.v4.u32 {%0,%1,%2,%3}, [%4];"
                 : "=r"(r[0]), "=r"(r[1]), "=r"(r[2]), "=r"(r[3]) : "r"(a));
}
__device__ __forceinline__ void sts64(uint32_t a, float x, float y) {
    asm volatile("st.shared.v2.f32 [%0], {%1, %2};" :: "r"(a), "f"(x), "f"(y));
}
__device__ __forceinline__ uint32_t rna(uint32_t x) {
    uint32_t y;
    asm("cvt.rna.tf32.f32 %0, %1;" : "=r"(y) : "r"(x));
    return y;
}
__device__ __forceinline__ float rna_f(float v) {
    return __uint_as_float(rna(__float_as_uint(v)));
}
__device__ __forceinline__ void mma_tf32(float c[4], const uint32_t a[4],
                                         uint32_t b0, uint32_t b1) {
    asm volatile(
        "mma.sync.aligned.m16n8k8.row.col.f32.tf32.tf32.f32 "
        "{%0,%1,%2,%3}, {%4,%5,%6,%7}, {%8,%9}, {%0,%1,%2,%3};"
        : "+f"(c[0]), "+f"(c[1]), "+f"(c[2]), "+f"(c[3])
        : "r"(a[0]), "r"(a[1]), "r"(a[2]), "r"(a[3]), "r"(b0), "r"(b1));
}

// ---------------- Kernel 1: degree -> dnorm ----------------
__global__ void deg_kernel(const float* __restrict__ adj) {
    int row  = blockIdx.x * 8 + (threadIdx.x >> 5);
    int lane = threadIdx.x & 31;
    const float4* p = (const float4*)(adj + (size_t)row * NN);
    float s = 0.f;
#pragma unroll
    for (int i = 0; i < 4; i++) {
        float4 v = p[lane + i * 32];
        s += (v.x + v.y) + (v.z + v.w);
    }
#pragma unroll
    for (int o = 16; o; o >>= 1) s += __shfl_xor_sync(0xffffffffu, s, o);
    if (lane == 0) g_dnorm[row] = (s > 0.f) ? rsqrtf(s) : 0.f;
}

// ---------------- Kernel 2: W -> frag-linear W^T, tf32-rounded ----------------
__global__ void prep_w_kernel(const float* __restrict__ W) {
    int idx = blockIdx.x * 256 + threadIdx.x;   // 16 blocks x 256 = 4096 float4s
    int k8 = idx >> 8, jj = (idx >> 5) & 7, gid = (idx >> 2) & 7, tq = idx & 3;
    int n0 = jj * 16 + gid, n1 = n0 + 8;
    int k = k8 * 8 + tq;
    float4 v;
    v.x = rna_f(W[k * FF + n0]);
    v.y = rna_f(W[(k + 4) * FF + n0]);
    v.z = rna_f(W[k * FF + n1]);
    v.w = rna_f(W[(k + 4) * FF + n1]);
    g_Wf[idx] = v;
}

// ---------------- Kernel 3: frag-linear h^T = (dnorm ⊙ x)^T, tf32-rounded ----------------
__global__ __launch_bounds__(256) void prep_h_kernel(const float* __restrict__ x) {
    __shared__ float s[64 * 132];
    int b  = blockIdx.x >> 3;
    int c8 = blockIdx.x & 7;          // 64-node chunk
    int k0 = c8 * 64;
    int tid = threadIdx.x;
    const float4* gx = (const float4*)(x + ((size_t)b * NN + k0) * FF);
#pragma unroll
    for (int i = 0; i < 8; i++) {
        int f = tid + i * 256;        // float4 idx in 64x128 tile
        int k = f >> 5, g4 = (f & 31) * 4;
        float4 v = gx[f];
        float dn = g_dnorm[b * NN + k0 + k];
        s[k * 132 + g4 + 0] = v.x * dn;
        s[k * 132 + g4 + 1] = v.y * dn;
        s[k * 132 + g4 + 2] = v.z * dn;
        s[k * 132 + g4 + 3] = v.w * dn;
    }
    __syncthreads();
    int jj = tid >> 5, gid = (tid >> 2) & 7, tq = tid & 3;
    int f0 = jj * 16 + gid, f1 = f0 + 8;
#pragma unroll
    for (int k8l = 0; k8l < 8; k8l++) {
        int kl = k8l * 8 + tq;
        float4 v;
        v.x = rna_f(s[kl * 132 + f0]);
        v.y = rna_f(s[(kl + 4) * 132 + f0]);
        v.z = rna_f(s[kl * 132 + f1]);
        v.w = rna_f(s[(kl + 4) * 132 + f1]);
        g_hTf[(((size_t)b * 64 + c8 * 8 + k8l) * 8 + jj) * 32 + gid * 4 + tq] = v;
    }
}

// ---------------- Fused: t = adj@h (tf32, K=512); out = relu(dn*(t@W)+b) ----------------
// 512 threads, warp grid 4x4, warp tile 32x32, frag double-buffered mainloop.
// smem phase 1: 3 stages x 34816 B:
//   A adj fp32 [128r x 32k, stride 144B] (18432 B) + B hT frags linear (16384 B)
// smem phase 2: A2 (t fp32) at 0, stride 528B (67584 B);
//   W frag half (8 k8 x 4096 B = 32768) at 67584. Peak 100352 <= 104448.
#define STG 34816
#define BOFF 18432
#define ASTRIDE 144
#define A2STRIDE 528
#define WOFF2 67584
#define FUSED_SMEM (3 * STG)

__global__ __launch_bounds__(512)
void fused_kernel(const float* __restrict__ adj, const float* __restrict__ bias,
                  float* __restrict__ out) {
    extern __shared__ char sm[];
    uint32_t sbu = smem_u32(sm);
    int tid = threadIdx.x, lane = tid & 31, wid = tid >> 5;
    int warp_m = wid & 3, warp_n = wid >> 2;   // 4 x 4 warps, warp tile 32x32
    int gid = lane >> 2, tq = lane & 3;
    int bb = blockIdx.x >> 2, m0 = (blockIdx.x & 3) * 128;

    const char* adjb = (const char*)adj;
    const char* hfb = (const char*)g_hTf;
    const char* wfb = (const char*)g_Wf;

    auto load_stage = [&](int s) {
        uint32_t base = sbu + (s % 3) * STG;
#pragma unroll
        for (int i = 0; i < 2; i++) {                 // adj: 128 rows x 32 floats
            int c = tid + i * 512;                    // 0..1023
            int row = c >> 3, ch = c & 7;
            cp16(base + row * ASTRIDE + ch * 16,
                 adjb + ((size_t)(bb * NN + m0 + row) * NN + s * 32) * 4 + ch * 16);
        }
#pragma unroll
        for (int i = 0; i < 2; i++) {                 // hT frags: 16 KB linear
            int c = tid + i * 512;
            cp16(base + BOFF + c * 16,
                 hfb + ((size_t)(bb * 64 + s * 4)) * 4096 + c * 16);
        }
    };
    auto load_w_half = [&](int half) {
#pragma unroll
        for (int i = 0; i < 4; i++) {
            int c = tid + i * 512;                    // 0..2047 chunks, 32 KB
            cp16(sbu + WOFF2 + c * 16, wfb + (size_t)(half * 2048 + c) * 16);
        }
    };

    // fragment loaders (double-buffered)
    auto p1_loadB = [&](uint32_t base, int k8, uint32_t (&fb)[2][4]) {
        uint32_t a0 = base + BOFF + k8 * 4096 + (warp_n * 2) * 512 + gid * 64 + tq * 16;
        lds128(fb[0], a0);
        lds128(fb[1], a0 + 512);
    };
    auto p1_loadA = [&](uint32_t base, int k8, uint32_t (&fa)[2][4]) {
#pragma unroll
        for (int i = 0; i < 2; i++) {
            uint32_t aa = base + (warp_m * 32 + i * 16 + gid) * ASTRIDE + (k8 * 8 + tq) * 4;
            fa[i][0] = rna(lds32(aa));
            fa[i][1] = rna(lds32(aa + 8 * ASTRIDE));
            fa[i][2] = rna(lds32(aa + 16));
            fa[i][3] = rna(lds32(aa + 8 * ASTRIDE + 16));
        }
    };
    auto p2_loadW = [&](int kk, uint32_t (&fb)[2][4]) {
        uint32_t a0 = sbu + WOFF2 + (kk & 7) * 4096 + (warp_n * 2) * 512 + gid * 64 + tq * 16;
        lds128(fb[0], a0);
        lds128(fb[1], a0 + 512);
    };
    auto p2_loadA = [&](int k8, uint32_t (&fa)[2][4]) {
#pragma unroll
        for (int i = 0; i < 2; i++) {
            uint32_t aa = sbu + (warp_m * 32 + i * 16 + gid) * A2STRIDE + (k8 * 8 + tq) * 4;
            fa[i][0] = rna(lds32(aa));
            fa[i][1] = rna(lds32(aa + 8 * A2STRIDE));
            fa[i][2] = rna(lds32(aa + 16));
            fa[i][3] = rna(lds32(aa + 8 * A2STRIDE + 16));
        }
    };

    float C[2][4][4];
#pragma unroll
    for (int i = 0; i < 2; i++)
#pragma unroll
        for (int j = 0; j < 4; j++)
#pragma unroll
            for (int k = 0; k < 4; k++) C[i][j][k] = 0.f;

    auto do_mma = [&](uint32_t (&fa)[2][4], uint32_t (&fb)[2][4]) {
#pragma unroll
        for (int i = 0; i < 2; i++)
#pragma unroll
            for (int j = 0; j < 4; j++)
                mma_tf32(C[i][j], fa[i], fb[j >> 1][(j & 1) * 2], fb[j >> 1][(j & 1) * 2 + 1]);
    };

    load_stage(0); CP_COMMIT();
    load_stage(1); CP_COMMIT();
    load_stage(2); CP_COMMIT();

    uint32_t FA[2][2][4], FB[2][2][4];

    // ---- phase 1: t = adj @ h, K = 512 ----
    for (int s = 0; s < 16; s++) {
        if (s < 14) { CP_WAIT_2(); } else if (s == 14) { CP_WAIT_1(); } else { CP_WAIT_0(); }
        __syncthreads();
        uint32_t base = sbu + (s % 3) * STG;
        p1_loadB(base, 0, FB[0]);
        p1_loadA(base, 0, FA[0]);
#pragma unroll
        for (int k8 = 0; k8 < 4; k8++) {
            int cur = k8 & 1, nxt = cur ^ 1;
            if (k8 < 3) { p1_loadB(base, k8 + 1, FB[nxt]); p1_loadA(base, k8 + 1, FA[nxt]); }
            do_mma(FA[cur], FB[cur]);
        }
        __syncthreads();
        if (s + 3 < 16) { load_stage(s + 3); CP_COMMIT(); }
    }

    // ---- prefetch W frag half 0 (k8 0..7) ----
    load_w_half(0);
    CP_COMMIT();

    // ---- epilogue 1: C (= t tile) -> smem fp32 A2; zero C for phase 2 ----
#pragma unroll
    for (int i = 0; i < 2; i++) {
        int r0 = warp_m * 32 + i * 16 + gid;
#pragma unroll
        for (int j = 0; j < 4; j++) {
            int cc = warp_n * 32 + j * 8 + tq * 2;
            sts64(sbu + r0 * A2STRIDE + cc * 4, C[i][j][0], C[i][j][1]);
            sts64(sbu + (r0 + 8) * A2STRIDE + cc * 4, C[i][j][2], C[i][j][3]);
            C[i][j][0] = C[i][j][1] = C[i][j][2] = C[i][j][3] = 0.f;
        }
    }
    CP_WAIT_0();
    __syncthreads();

    // ---- phase 2: out = t @ W (K = 128, two k8-halves; W frags reloaded between) ----
#pragma unroll 1
    for (int half = 0; half < 2; half++) {
        p2_loadW(0, FB[0]);
        p2_loadA(half * 8, FA[0]);
#pragma unroll
        for (int kk = 0; kk < 8; kk++) {
            int cur = kk & 1, nxt = cur ^ 1;
            if (kk < 7) { p2_loadW(kk + 1, FB[nxt]); p2_loadA(half * 8 + kk + 1, FA[nxt]); }
            do_mma(FA[cur], FB[cur]);
        }
        if (half == 0) {
            __syncthreads();             // all warps done reading W half 0
            load_w_half(1);
            CP_COMMIT();
            CP_WAIT_0();
            __syncthreads();
        }
    }

    // ---- epilogue 2: relu(dnorm * acc + bias) -> out ----
#pragma unroll
    for (int i = 0; i < 2; i++) {
        int r0 = warp_m * 32 + i * 16 + gid;
        int node0 = m0 + r0, node1 = node0 + 8;
        float dn0 = g_dnorm[bb * NN + node0];
        float dn1 = g_dnorm[bb * NN + node1];
#pragma unroll
        for (int j = 0; j < 4; j++) {
            int g = warp_n * 32 + j * 8 + tq * 2;
            float b0 = bias[g], b1 = bias[g + 1];
            float2 v0, v1;
            v0.x = fmaxf(dn0 * C[i][j][0] + b0, 0.f);
            v0.y = fmaxf(dn0 * C[i][j][1] + b1, 0.f);
            v1.x = fmaxf(dn1 * C[i][j][2] + b0, 0.f);
            v1.y = fmaxf(dn1 * C[i][j][3] + b1, 0.f);
            *(float2*)(out + ((size_t)(bb * NN + node0)) * FF + g) = v0;
            *(float2*)(out + ((size_t)(bb * NN + node1)) * FF + g) = v1;
        }
    }
}

// ---------------- launch ----------------
extern "C" void kernel_launch(void* const* d_in, const int* in_sizes, int n_in,
                              void* d_out, int out_size) {
    const float* adj  = (const float*)d_in[0];
    const float* x    = (const float*)d_in[1];
    const float* W    = (const float*)d_in[2];
    const float* bias = (const float*)d_in[3];
    float* out = (float*)d_out;

    cudaFuncSetAttribute(fused_kernel, cudaFuncAttributeMaxDynamicSharedMemorySize,
                         FUSED_SMEM);

    deg_kernel<<<(BB * NN) / 8, 256>>>(adj);
    prep_w_kernel<<<16, 256>>>(W);
    prep_h_kernel<<<BB * 8, 256>>>(x);
    fused_kernel<<<BB * 4, 512, FUSED_SMEM>>>(adj, bias, out);
}